// round 9
// baseline (speedup 1.0000x reference)
#include <cuda_runtime.h>
#include <math.h>
#include <stdint.h>

#define DDIM 2048
#define NROWS 65536
#define WARPS_PB 8
#define NSTAGES 3
#define ROWS_PER_STAGE 8               // one row per warp per stage
#define STAGE_BYTES (ROWS_PER_STAGE * DDIM * 4)   // 65536
#define STAGE_UNITS (NROWS / ROWS_PER_STAGE)      // 8192 per side
#define MAX_CHUNKS 96                  // >= blocks per side for any SM count
#define ALIGN_BLKS 256
#define ALIGN_ROWS (DDIM / ALIGN_BLKS) // 8

// -------- device scratch (no allocations allowed) --------
__device__ float g_align_part[ALIGN_BLKS][2][DDIM];     // 4 MB
__device__ float g_align[2][DDIM];
__device__ float g_acc[2][MAX_CHUNKS][DDIM];            // 1.5 MB
__device__ float g_m[2][MAX_CHUNKS];
__device__ float g_z[2][MAX_CHUNKS];

// -------- PTX helpers --------
__device__ __forceinline__ uint32_t smem_u32(const void* p) {
    return (uint32_t)__cvta_generic_to_shared(p);
}
#define MBAR_INIT(addr, cnt) \
    asm volatile("mbarrier.init.shared.b64 [%0], %1;" :: "r"(addr), "r"(cnt) : "memory")
#define MBAR_EXPECT_TX(addr, bytes) \
    asm volatile("mbarrier.arrive.expect_tx.shared.b64 _, [%0], %1;" :: "r"(addr), "r"(bytes) : "memory")
#define BULK_G2S(dst, src, bytes, mbar) \
    asm volatile("cp.async.bulk.shared::cta.global.mbarrier::complete_tx::bytes [%0], [%1], %2, [%3];" \
                 :: "r"(dst), "l"(src), "r"(bytes), "r"(mbar) : "memory")
#define MBAR_WAIT_PARITY(addr, parity) do {                                        \
    uint32_t _m = (addr); uint32_t _p = (parity); uint32_t _done;                  \
    asm volatile("{\n\t.reg .pred p;\n\t"                                          \
        "mbarrier.try_wait.parity.acquire.cta.shared::cta.b64 p, [%1], %2;\n\t"    \
        "selp.b32 %0, 1, 0, p;\n\t}"                                               \
        : "=r"(_done) : "r"(_m), "r"(_p) : "memory");                              \
    if (!_done) {                                                                  \
        asm volatile("{\n\t.reg .pred P1;\n\t"                                     \
            "WL_%=:\n\t"                                                           \
            "mbarrier.try_wait.parity.acquire.cta.shared::cta.b64 P1, [%0], %1, 0x989680;\n\t" \
            "@P1 bra.uni WD_%=;\n\t"                                               \
            "bra.uni WL_%=;\n\t"                                                   \
            "WD_%=:\n\t}" :: "r"(_m), "r"(_p) : "memory");                         \
    }                                                                              \
} while (0)
#define BAR_ARRIVE(id) \
    asm volatile("bar.arrive %0, 256;" :: "r"(id) : "memory")
#define BAR_SYNC(id) \
    asm volatile("bar.sync %0, 256;" :: "r"(id) : "memory")

// ---------------------------------------------------------
// Kernel 1: partial GEMV for both sides against shared W_a.
// ---------------------------------------------------------
__global__ void align_partial(const float* __restrict__ wl,
                              const float* __restrict__ wr,
                              const float* __restrict__ Wa) {
    int b = blockIdx.x;
    int t = threadIdx.x;
    float accl[8], accr[8];
#pragma unroll
    for (int k = 0; k < 8; k++) { accl[k] = 0.f; accr[k] = 0.f; }

    int r0 = b * ALIGN_ROWS;
#pragma unroll
    for (int i = 0; i < ALIGN_ROWS; i++) {
        int row = r0 + i;
        float vl = wl[row];
        float vr = wr[row];
        const float* Wrow = Wa + (size_t)row * DDIM;
#pragma unroll
        for (int k = 0; k < 8; k++) {
            float w = Wrow[t + 256 * k];
            accl[k] = fmaf(vl, w, accl[k]);
            accr[k] = fmaf(vr, w, accr[k]);
        }
    }
#pragma unroll
    for (int k = 0; k < 8; k++) {
        g_align_part[b][0][t + 256 * k] = accl[k];
        g_align_part[b][1][t + 256 * k] = accr[k];
    }
}

// ---------------------------------------------------------
// Kernel 2: reduce align partials, add bias, tanh.
// ---------------------------------------------------------
__global__ void align_finalize(const float* __restrict__ ba) {
    int j = blockIdx.x * blockDim.x + threadIdx.x;
    float bias = ba[j];
    float sl = bias, sr = bias;
    for (int b = 0; b < ALIGN_BLKS; b++) {
        sl += g_align_part[b][0][j];
        sr += g_align_part[b][1][j];
    }
    g_align[0][j] = tanhf(sl);
    g_align[1][j] = tanhf(sr);
}

// ---------------------------------------------------------
// Kernel 3: LONG-STREAM fused score + online-softmax + accumulate.
// gridDim.x blocks (== SM count, even). Blocks [0, H) handle side 0
// (word_l vs candR), blocks [H, 2H) side 1, H = gridDim.x/2.
// Block i owns contiguous stage-units [i*8192/H, (i+1)*8192/H).
// Per-stage slot release is DECOUPLED: consumer warps bar.arrive
// (non-blocking) and run ahead; only warp 0 bar.syncs before the
// refetch. Barrier ids rotate mod 4 (max consumer lead 2 < 4).
// TMA prologue is issued BEFORE the align smem load to overlap
// startup. Exactly ONE 8-warp merge per block at the end.
// ---------------------------------------------------------
extern __shared__ float dynsmem[];     // NSTAGES * 64 KB ring; slot 0 reused for merge

__global__ void __launch_bounds__(256, 1)
attn_stream(const float* __restrict__ candL, const float* __restrict__ candR) {
    const int H    = gridDim.x >> 1;
    const int side = (blockIdx.x >= H) ? 1 : 0;
    const int idx  = blockIdx.x - side * H;
    const float* cand = side ? candL : candR;
    const int tid  = threadIdx.x;
    const int warp = tid >> 5;
    const int lane = tid & 31;

    const int s0 = (int)(((long long)idx * STAGE_UNITS) / H);
    const int s1 = (int)(((long long)(idx + 1) * STAGE_UNITS) / H);
    const int ns = s1 - s0;            // ~108 stages

    __shared__ float s_align[DDIM];    // 8 KB (this block's side only)
    __shared__ float s_m[WARPS_PB], s_z[WARPS_PB];
    __shared__ uint64_t s_mbar[NSTAGES];

    if (tid == 0) {
#pragma unroll
        for (int s = 0; s < NSTAGES; s++)
            MBAR_INIT(smem_u32(&s_mbar[s]), 1);
    }
    __syncthreads();

    // TMA prologue FIRST: overlap the fetches with the align load below.
    if (tid == 0) {
        int pre = ns < NSTAGES ? ns : NSTAGES;
        for (int g = 0; g < pre; g++) {
            uint32_t mb = smem_u32(&s_mbar[g]);
            MBAR_EXPECT_TX(mb, STAGE_BYTES);
            BULK_G2S(smem_u32(dynsmem) + g * STAGE_BYTES,
                     cand + (size_t)(s0 + g) * ROWS_PER_STAGE * DDIM,
                     STAGE_BYTES, mb);
        }
    }

    for (int i = tid; i < DDIM; i += 256)
        s_align[i] = g_align[side][i];
    __syncthreads();

    // align slice in registers: lane l owns cols {4l + 128c}
    float4 al[16];
    {
        const float4* ap = reinterpret_cast<const float4*>(s_align) + lane;
#pragma unroll
        for (int c = 0; c < 16; c++) al[c] = ap[c * 32];
    }

    float4 acc[16];
#pragma unroll
    for (int c = 0; c < 16; c++) acc[c] = make_float4(0.f, 0.f, 0.f, 0.f);
    float m = -1e30f, Z = 0.f;

    for (int g = 0; g < ns; g++) {
        const int slot = g % NSTAGES;
        const int bar_id = 1 + (g & 3);
        MBAR_WAIT_PARITY(smem_u32(&s_mbar[slot]), (g / NSTAGES) & 1);

        const float4* rp = reinterpret_cast<const float4*>(
            dynsmem + slot * (STAGE_BYTES / 4) + warp * DDIM) + lane;

        float4 x[16];
#pragma unroll
        for (int c = 0; c < 16; c++) x[c] = rp[c * 32];

        float p0 = 0.f, p1 = 0.f, p2 = 0.f, p3 = 0.f;
#pragma unroll
        for (int c = 0; c < 16; c++) {
            p0 = fmaf(x[c].x, al[c].x, p0);
            p1 = fmaf(x[c].y, al[c].y, p1);
            p2 = fmaf(x[c].z, al[c].z, p2);
            p3 = fmaf(x[c].w, al[c].w, p3);
        }
        float p = (p0 + p1) + (p2 + p3);
#pragma unroll
        for (int o = 16; o > 0; o >>= 1)
            p += __shfl_xor_sync(0xffffffffu, p, o);

        if (p > m) {
            float c = __expf(m - p);   // first row: exp(-huge) == 0
            Z *= c;
#pragma unroll
            for (int k = 0; k < 16; k++) {
                acc[k].x *= c; acc[k].y *= c; acc[k].z *= c; acc[k].w *= c;
            }
            m = p;
        }
        float w = __expf(p - m);
        Z += w;
#pragma unroll
        for (int k = 0; k < 16; k++) {
            acc[k].x = fmaf(w, x[k].x, acc[k].x);
            acc[k].y = fmaf(w, x[k].y, acc[k].y);
            acc[k].z = fmaf(w, x[k].z, acc[k].z);
            acc[k].w = fmaf(w, x[k].w, acc[k].w);
        }
        // NOTE: every x[] value above is consumed by FMAs, so in-order
        // issue guarantees the LDS performed before we release the slot.

        if (warp != 0) {
            BAR_ARRIVE(bar_id);        // non-blocking: run ahead
        } else {
            BAR_SYNC(bar_id);          // all 8 warps drained this slot
            if (tid == 0 && g + NSTAGES < ns) {
                uint32_t mb = smem_u32(&s_mbar[slot]);
                MBAR_EXPECT_TX(mb, STAGE_BYTES);
                BULK_G2S(smem_u32(dynsmem) + slot * STAGE_BYTES,
                         cand + (size_t)(s0 + g + NSTAGES) * ROWS_PER_STAGE * DDIM,
                         STAGE_BYTES, mb);
            }
        }
    }

    // ---- ONE block-level merge of the 8 warp states ----
    if (lane == 0) { s_m[warp] = m; s_z[warp] = Z; }
    __syncthreads();

    float mb2 = s_m[0];
#pragma unroll
    for (int w = 1; w < WARPS_PB; w++) mb2 = fmaxf(mb2, s_m[w]);
    float scale = __expf(m - mb2);     // warp-uniform

    float* s_acc = dynsmem;            // 64 KB merge buffer (ring slot 0)
    float4* sa = reinterpret_cast<float4*>(s_acc + warp * DDIM) + lane;
#pragma unroll
    for (int c = 0; c < 16; c++) {
        float4 v = acc[c];
        v.x *= scale; v.y *= scale; v.z *= scale; v.w *= scale;
        sa[c * 32] = v;
    }
    __syncthreads();

    for (int j = tid; j < DDIM; j += 256) {
        float ssum = 0.f;
#pragma unroll
        for (int w = 0; w < WARPS_PB; w++) ssum += s_acc[w * DDIM + j];
        g_acc[side][idx][j] = ssum;
    }
    if (tid == 0) {
        float zb = 0.f;
#pragma unroll
        for (int w = 0; w < WARPS_PB; w++)
            zb += s_z[w] * __expf(s_m[w] - mb2);
        g_m[side][idx] = mb2;
        g_z[side][idx] = zb;
    }
}

// ---------------------------------------------------------
// Kernel 4: single tail kernel. grid (32, 2), 256 threads.
// H chunks per side (~74-76). Stats over H entries are tiny:
// every thread serially reduces the smem copies (~H LDS), then
// 16-way chunk-partitioned reduction of g_acc for a 64-col tile.
// out layout: [0..2047] = left result, [2048..4095] = right.
// ---------------------------------------------------------
__global__ void __launch_bounds__(256, 4)
combine_all(float* __restrict__ out, int H) {
    const int side = blockIdx.y;
    const int t    = threadIdx.x;
    const int f4   = t & 15;           // float4 column within 64-col tile
    const int part = t >> 4;           // 0..15

    __shared__ float s_mv[MAX_CHUNKS];
    __shared__ float s_zv[MAX_CHUNKS];
    __shared__ float s_coef[MAX_CHUNKS];
    __shared__ float4 s_part[16][16];

    if (t < H) { s_mv[t] = g_m[side][t]; s_zv[t] = g_z[side][t]; }
    __syncthreads();

    float M = -1e30f;
    for (int c = 0; c < H; c++) M = fmaxf(M, s_mv[c]);
    float Zt = 0.f;
    for (int c = 0; c < H; c++) Zt += s_zv[c] * __expf(s_mv[c] - M);
    float Zi = 1.0f / Zt;
    if (t < H) s_coef[t] = __expf(s_mv[t] - M) * Zi;
    __syncthreads();

    const int col4 = blockIdx.x * 16 + f4;          // float4 col in [0,512)
    const float4* ap = reinterpret_cast<const float4*>(&g_acc[side][0][0]) + col4;

    float4 s = make_float4(0.f, 0.f, 0.f, 0.f);
    for (int c = part; c < H; c += 16) {
        float4 v = ap[(size_t)c * (DDIM / 4)];
        float k = s_coef[c];
        s.x = fmaf(k, v.x, s.x);
        s.y = fmaf(k, v.y, s.y);
        s.z = fmaf(k, v.z, s.z);
        s.w = fmaf(k, v.w, s.w);
    }
    s_part[part][f4] = s;
    __syncthreads();

#pragma unroll
    for (int o = 8; o > 0; o >>= 1) {
        if (part < o) {
            float4 a = s_part[part][f4];
            float4 bb = s_part[part + o][f4];
            a.x += bb.x; a.y += bb.y; a.z += bb.z; a.w += bb.w;
            s_part[part][f4] = a;
        }
        __syncthreads();
    }

    if (part == 0)
        reinterpret_cast<float4*>(out)[side * (DDIM / 4) + col4] = s_part[0][f4];
}

// ---------------------------------------------------------
extern "C" void kernel_launch(void* const* d_in, const int* in_sizes, int n_in,
                              void* d_out, int out_size) {
    const float* wl    = (const float*)d_in[0];  // embed_word_l  [1, D]
    const float* wr    = (const float*)d_in[1];  // embed_word_r  [1, D]
    const float* candL = (const float*)d_in[2];  // embed_candidates_l [N, D]
    const float* candR = (const float*)d_in[3];  // embed_candidates_r [N, D]
    const float* Wa    = (const float*)d_in[4];  // W_a [D, D]
    const float* ba    = (const float*)d_in[5];  // b_a [1, D]
    float* out = (float*)d_out;

    static int grid_attn = 0;          // set once; deterministic per device
    if (!grid_attn) {
        int sm = 0;
        cudaDeviceGetAttribute(&sm, cudaDevAttrMultiProcessorCount, 0);
        if (sm <= 0) sm = 148;
        grid_attn = sm & ~1;           // even: half per side
        if (grid_attn > 2 * MAX_CHUNKS) grid_attn = 2 * MAX_CHUNKS;
        cudaFuncSetAttribute(attn_stream,
                             cudaFuncAttributeMaxDynamicSharedMemorySize,
                             NSTAGES * STAGE_BYTES);
    }
    const int H = grid_attn / 2;

    align_partial<<<ALIGN_BLKS, 256>>>(wl, wr, Wa);
    align_finalize<<<DDIM / 256, 256>>>(ba);
    attn_stream<<<grid_attn, 256, NSTAGES * STAGE_BYTES>>>(candL, candR);
    combine_all<<<dim3(DDIM / 64, 2), 256>>>(out, H);
}